// round 14
// baseline (speedup 1.0000x reference)
#include <cuda_runtime.h>
#include <cuda_bf16.h>
#include <cstdint>

#define B_   64
#define ORD  2
#define S_   256
#define D_   256
#define H_   8
#define HD_  32
#define M_   (B_ * S_)

// ---------------- device scratch (allocation-free) ----------------
__device__ float g_xp[4][M_ * D_];            // projected x (+bias), fp32
__device__ float2 g_esp[4][M_ * H_];          // (exp(as), exp(0.2 as)) per source
__device__ float2 g_edp[4][M_ * H_];          // (exp(ad), exp(0.2 ad)) per dest
__device__ __nv_bfloat16 g_xh[2][M_ * D_];    // x split hi  [m][k]
__device__ __nv_bfloat16 g_xl[2][M_ * D_];    // x split lo
__device__ __nv_bfloat16 g_wh[4][D_ * D_];    // W^T split hi [n][k]
__device__ __nv_bfloat16 g_wl[4][D_ * D_];    // W^T split lo
__device__ __nv_bfloat16 g_xvh[4][M_ * D_];   // values transposed bf16 [(b*H+h)*HD+d][s]

// ---------------- helpers ----------------
__device__ __forceinline__ uint32_t smem_u32(const void* p) {
    uint32_t a;
    asm("{ .reg .u64 t; cvta.to.shared.u64 t, %1; cvt.u32.u64 %0, t; }"
        : "=r"(a) : "l"(p));
    return a;
}
__device__ __forceinline__ void mma16816(float* c, const uint32_t a0, const uint32_t a1,
                                         const uint32_t a2, const uint32_t a3,
                                         const uint32_t b0, const uint32_t b1) {
    asm volatile(
        "mma.sync.aligned.m16n8k16.row.col.f32.bf16.bf16.f32 "
        "{%0,%1,%2,%3}, {%4,%5,%6,%7}, {%8,%9}, {%0,%1,%2,%3};"
        : "+f"(c[0]), "+f"(c[1]), "+f"(c[2]), "+f"(c[3])
        : "r"(a0), "r"(a1), "r"(a2), "r"(a3), "r"(b0), "r"(b1));
}
__device__ __forceinline__ void ldsm_x4(uint32_t& r0, uint32_t& r1, uint32_t& r2,
                                        uint32_t& r3, uint32_t addr) {
    asm volatile("ldmatrix.sync.aligned.m8n8.x4.shared.b16 {%0,%1,%2,%3}, [%4];"
                 : "=r"(r0), "=r"(r1), "=r"(r2), "=r"(r3) : "r"(addr));
}
__device__ __forceinline__ void ldsm_x2(uint32_t& r0, uint32_t& r1, uint32_t addr) {
    asm volatile("ldmatrix.sync.aligned.m8n8.x2.shared.b16 {%0,%1}, [%2];"
                 : "=r"(r0), "=r"(r1) : "r"(addr));
}
#define CP_ASYNC16(dst, src) \
    asm volatile("cp.async.ca.shared.global [%0], [%1], 16;" \
                 :: "r"(dst), "l"(src) : "memory")
#define CP_COMMIT() asm volatile("cp.async.commit_group;" ::: "memory")
#define CP_WAIT1() asm volatile("cp.async.wait_group 1;" ::: "memory")
#define CP_WAIT0() asm volatile("cp.async.wait_group 0;" ::: "memory")

// ---------------------------------------------------------------------------
// split-conversion kernels
// ---------------------------------------------------------------------------
__global__ void convert_x_kernel(const float* __restrict__ x) {
    long q = (long)blockIdx.x * 256 + threadIdx.x;   // float4 index
    float4 v = ((const float4*)x)[q];
    long e = q * 4;
    int d = (int)(e & 255);
    long sd = e >> 8;
    int s = (int)(sd & 255);
    int bi = (int)(sd >> 8);
    int i = bi & 1, b = bi >> 1;
    long o = ((long)(b * 256 + s)) * 256 + d;
    union { __nv_bfloat16 h[4]; uint2 u; } ph, pl;
    float f[4] = {v.x, v.y, v.z, v.w};
    #pragma unroll
    for (int t = 0; t < 4; t++) {
        __nv_bfloat16 hi = __float2bfloat16(f[t]);
        ph.h[t] = hi;
        pl.h[t] = __float2bfloat16(f[t] - __bfloat162float(hi));
    }
    *(uint2*)&g_xh[i][o] = ph.u;
    *(uint2*)&g_xl[i][o] = pl.u;
}

__global__ void convert_w_kernel(const float* __restrict__ Wp) {
    int idx = blockIdx.x * 256 + threadIdx.x;   // 4*65536 total
    int ij = idx >> 16;
    int r = idx & 65535;
    int k = r >> 8, n = r & 255;
    float v = Wp[idx];
    __nv_bfloat16 hi = __float2bfloat16(v);
    g_wh[ij][n * 256 + k] = hi;
    g_wl[ij][n * 256 + k] = __float2bfloat16(v - __bfloat162float(hi));
}

// ---------------------------------------------------------------------------
// projection via mma.sync, cp.async double-buffered staging,
// + fused score exps (es, es^0.2 / ed, ed^0.2) + transposed value emit (bf16)
// grid (M/128, D/64, 4), 256 threads (8 warps, wm 0..3 x wn 0..1)
// ---------------------------------------------------------------------------
#define LDA_P 40    // padded k-stride (bf16 elems)
#define LDT_P 136   // padded s-stride for transpose stage
#define PSTG  30720
#define P_TOTAL (2 * PSTG)
__global__ void __launch_bounds__(256) proj_mma_kernel(
        const float* __restrict__ bp,
        const float* __restrict__ att_src,
        const float* __restrict__ att_dst) {
    extern __shared__ __align__(16) char psm[];
    __nv_bfloat16* Th = (__nv_bfloat16*)(psm);   // 64*136*2 = 17408 B reuse

    const int tid = threadIdx.x;
    const int wid = tid >> 5, lane = tid & 31;
    const int wm = wid & 3, wn = wid >> 2;
    const int m0 = blockIdx.x * 128;
    const int n0 = blockIdx.y * 64;
    const int ij = blockIdx.z;
    const int i = ij >> 1;
    const int r4 = lane >> 2, c2 = (lane & 3) * 2;
    const int b = m0 >> 8, s0 = m0 & 255;
    const int h0 = n0 >> 5;
    const int hw = h0 + wn;

    const __nv_bfloat16* xh = g_xh[i];
    const __nv_bfloat16* xl = g_xl[i];
    const __nv_bfloat16* wh = g_wh[ij];
    const __nv_bfloat16* wl = g_wl[ij];

    const uint32_t sb = smem_u32(psm);
    const int tq = lane >> 3, rq = lane & 7;
    uint32_t aA0[2], aB0[2];
    #pragma unroll
    for (int mt = 0; mt < 2; mt++)
        aA0[mt] = sb + ((wm * 32 + mt * 16 + (tq & 1) * 8 + rq) * LDA_P
                        + (tq >> 1) * 8) * 2;
    #pragma unroll
    for (int np = 0; np < 2; np++)
        aB0[np] = sb + 20480 + ((wn * 32 + np * 16 + (tq & 1) * 8 + rq) * LDA_P
                                + (tq >> 1) * 8) * 2;

    const int arow = tid >> 2, apart = tid & 3;
    const int brow = tid >> 2, bpart = tid & 3;

    float c[2][4][4] = {};

    // prologue: stage kc=0 into buffer 0
    {
        #pragma unroll
        for (int r = 0; r < 2; r++) {
            int row = arow + r * 64;
            long gi = (long)(m0 + row) * 256 + apart * 8;
            uint32_t dst = sb + row * 80 + apart * 16;
            CP_ASYNC16(dst, xh + gi);
            CP_ASYNC16(dst + 10240, xl + gi);
        }
        {
            long gi = (long)(n0 + brow) * 256 + bpart * 8;
            uint32_t dst = sb + 20480 + brow * 80 + bpart * 16;
            CP_ASYNC16(dst, wh + gi);
            CP_ASYNC16(dst + 5120, wl + gi);
        }
        CP_COMMIT();
    }

    for (int kc = 0; kc < 8; kc++) {
        const uint32_t boff = (kc & 1) * PSTG;
        CP_WAIT0();
        __syncthreads();
        if (kc < 7) {
            const int k0 = (kc + 1) * 32;
            const uint32_t nboff = ((kc + 1) & 1) * PSTG;
            #pragma unroll
            for (int r = 0; r < 2; r++) {
                int row = arow + r * 64;
                long gi = (long)(m0 + row) * 256 + k0 + apart * 8;
                uint32_t dst = sb + nboff + row * 80 + apart * 16;
                CP_ASYNC16(dst, xh + gi);
                CP_ASYNC16(dst + 10240, xl + gi);
            }
            {
                long gi = (long)(n0 + brow) * 256 + k0 + bpart * 8;
                uint32_t dst = sb + nboff + 20480 + brow * 80 + bpart * 16;
                CP_ASYNC16(dst, wh + gi);
                CP_ASYNC16(dst + 5120, wl + gi);
            }
            CP_COMMIT();
        }

        #pragma unroll
        for (int kt = 0; kt < 2; kt++) {
            const uint32_t off = boff + kt * 32;
            uint32_t ah[2][4], al[2][4], bh[4][2], bl[4][2];
            #pragma unroll
            for (int mt = 0; mt < 2; mt++) {
                ldsm_x4(ah[mt][0], ah[mt][1], ah[mt][2], ah[mt][3], aA0[mt] + off);
                ldsm_x4(al[mt][0], al[mt][1], al[mt][2], al[mt][3], aA0[mt] + 10240 + off);
            }
            #pragma unroll
            for (int np = 0; np < 2; np++) {
                ldsm_x4(bh[2 * np][0], bh[2 * np + 1][0],
                        bh[2 * np][1], bh[2 * np + 1][1], aB0[np] + off);
                ldsm_x4(bl[2 * np][0], bl[2 * np + 1][0],
                        bl[2 * np][1], bl[2 * np + 1][1], aB0[np] + 5120 + off);
            }
            #pragma unroll
            for (int mt = 0; mt < 2; mt++)
                #pragma unroll
                for (int nt = 0; nt < 4; nt++) {
                    mma16816(c[mt][nt], ah[mt][0], ah[mt][1], ah[mt][2], ah[mt][3],
                             bh[nt][0], bh[nt][1]);
                    mma16816(c[mt][nt], ah[mt][0], ah[mt][1], ah[mt][2], ah[mt][3],
                             bl[nt][0], bl[nt][1]);
                    mma16816(c[mt][nt], al[mt][0], al[mt][1], al[mt][2], al[mt][3],
                             bh[nt][0], bh[nt][1]);
                }
        }
    }

    // ---- epilogue: bias, store xp, fused score exps, bf16 transpose ----
    float asw[4][2], adw[4][2];
    #pragma unroll
    for (int nt = 0; nt < 4; nt++) {
        int n = n0 + wn * 32 + nt * 8 + c2;
        float2 bb = *(const float2*)&bp[ij * 256 + n];
        float2 sw = *(const float2*)&att_src[ij * 256 + n];
        float2 dw = *(const float2*)&att_dst[ij * 256 + n];
        asw[nt][0] = sw.x; asw[nt][1] = sw.y;
        adw[nt][0] = dw.x; adw[nt][1] = dw.y;
        #pragma unroll
        for (int mt = 0; mt < 2; mt++) {
            c[mt][nt][0] += bb.x; c[mt][nt][1] += bb.y;
            c[mt][nt][2] += bb.x; c[mt][nt][3] += bb.y;
        }
    }
    float* xp = g_xp[ij];
    #pragma unroll
    for (int mt = 0; mt < 2; mt++) {
        int m = m0 + wm * 32 + mt * 16 + r4;
        #pragma unroll
        for (int nt = 0; nt < 4; nt++) {
            int n = n0 + wn * 32 + nt * 8 + c2;
            *(float2*)&xp[(long)m * 256 + n]       = *(float2*)&c[mt][nt][0];
            *(float2*)&xp[(long)(m + 8) * 256 + n] = *(float2*)&c[mt][nt][2];
        }
    }
    #pragma unroll
    for (int mt = 0; mt < 2; mt++)
        #pragma unroll
        for (int rr = 0; rr < 2; rr++) {
            float vs = 0.f, vd = 0.f;
            #pragma unroll
            for (int nt = 0; nt < 4; nt++) {
                vs += c[mt][nt][rr * 2 + 0] * asw[nt][0]
                    + c[mt][nt][rr * 2 + 1] * asw[nt][1];
                vd += c[mt][nt][rr * 2 + 0] * adw[nt][0]
                    + c[mt][nt][rr * 2 + 1] * adw[nt][1];
            }
            vs += __shfl_xor_sync(0xffffffffu, vs, 1);
            vs += __shfl_xor_sync(0xffffffffu, vs, 2);
            vd += __shfl_xor_sync(0xffffffffu, vd, 1);
            vd += __shfl_xor_sync(0xffffffffu, vd, 2);
            if ((lane & 3) == 0) {
                int m = m0 + wm * 32 + mt * 16 + rr * 8 + r4;
                g_esp[ij][(long)m * 8 + hw] = make_float2(__expf(vs), __expf(0.2f * vs));
                g_edp[ij][(long)m * 8 + hw] = make_float2(__expf(vd), __expf(0.2f * vd));
            }
        }
    __syncthreads();
    #pragma unroll
    for (int mt = 0; mt < 2; mt++)
        #pragma unroll
        for (int nt = 0; nt < 4; nt++)
            #pragma unroll
            for (int rr = 0; rr < 2; rr++)
                #pragma unroll
                for (int cc = 0; cc < 2; cc++) {
                    float v = c[mt][nt][rr * 2 + cc];
                    int dl = wn * 32 + nt * 8 + c2 + cc;
                    int sl = wm * 32 + mt * 16 + rr * 8 + r4;
                    Th[dl * LDT_P + sl] = __float2bfloat16(v);
                }
    __syncthreads();
    for (int q = tid; q < 1024; q += 256) {
        int row = q >> 4, off = q & 15;
        int h = h0 + (row >> 5), d = row & 31;
        long go = ((long)((b * 8 + h) * 32 + d)) * 256 + s0 + off * 8;
        *(int4*)&g_xvh[ij][go] = *(int4*)&Th[row * LDT_P + off * 8];
    }
}

// ---------------------------------------------------------------------------
// attention: factored-exp weights (no per-entry MUFU) ->
//            AV + denominator MMA; cp.async double-buffered bf16 X staging
// grid (8 t-tiles, ORD, B), 256 threads. dynamic smem 75776 B, 3 CTAs/SM.
// ---------------------------------------------------------------------------
#define LDA_A 264  // padded s-stride (bf16 elems)
#define O_WH   0
#define O_WL   16896
#define O_X    33792   // 2 buffers x 16896 -> end 67584
#define XBUF   16896
#define O_ESP  67584   // float2[256] = 2048
#define O_EDP  69632   // float2[512] = 4096
#define O_MT   73728   // maskT: 512 words = 2048 -> end 75776
#define O_MS   (O_X + XBUF)  // mask temp aliases X buffer 1 (prologue only)
#define A_TOTAL 75776
#define ONES_BF16X2 0x3F803F80u

__global__ void __launch_bounds__(256, 3) attn_kernel(const int* __restrict__ A,
                            const float* __restrict__ gbias,
                            float* __restrict__ out) {
    const int t0 = blockIdx.x * 32;
    const int i  = blockIdx.y;
    const int b  = blockIdx.z;
    const int tid = threadIdx.x;
    const int lane = tid & 31, wid = tid >> 5;
    const int r4 = lane >> 2, c2 = (lane & 3) * 2;
    const int mt = wid & 1, nt = wid >> 1;

    extern __shared__ __align__(16) char smc[];
    __nv_bfloat16* Wh = (__nv_bfloat16*)(smc + O_WH);
    __nv_bfloat16* Wl = (__nv_bfloat16*)(smc + O_WL);
    float2* esp_sm = (float2*)(smc + O_ESP);
    float2* edp_sm = (float2*)(smc + O_EDP);
    unsigned* maskT = (unsigned*)(smc + O_MT);
    unsigned* mtmp  = (unsigned*)(smc + O_MS);

    const uint32_t sb = smem_u32(smc);
    const int tq = lane >> 3, rq = lane & 7;
    const uint32_t aAh = sb + O_WH +
        (uint32_t)((mt * 16 + (tq & 1) * 8 + rq) * LDA_A + (tq >> 1) * 8) * 2;
    const uint32_t bOffInRow = (uint32_t)((nt * 8 + rq) * LDA_A + ((lane >> 3) & 1) * 8) * 2;

    // hoisted staging offsets (thread-constant)
    int soff[4];
    uint32_t doff[4];
    #pragma unroll
    for (int r = 0; r < 4; r++) {
        int q = r * 256 + tid;
        int d = q >> 5, sv = q & 31;
        soff[r] = d * 256 + sv * 8;
        doff[r] = (uint32_t)(d * LDA_A + sv * 8) * 2;
    }
    const __nv_bfloat16* xv0 = g_xvh[i * 2 + 0] + (long)b * 65536;
    const __nv_bfloat16* xv1 = g_xvh[i * 2 + 1] + (long)b * 65536;

    // ---- edge masks (both convs): mtmp[j*256+s] bit tp (aliases X buf1) ----
    {
        const int* Abase = A + ((long)(b * ORD + i) * S_) * S_ + t0;
        for (int k = 0; k < 32; k++) {
            int s = wid * 32 + k;
            int a = Abase[s * S_ + lane];
            unsigned m1 = __ballot_sync(0xffffffffu, (a == 2) | (a == 4));
            unsigned m2 = __ballot_sync(0xffffffffu, (a == 3) | (a == 4));
            if (lane == 0) { mtmp[s] = m1; mtmp[256 + s] = m2; }
        }
    }
    // prologue: X(h=0,j=0) into buffer 0 (does not touch buf1/mtmp)
    {
        #pragma unroll
        for (int r = 0; r < 4; r++)
            CP_ASYNC16(sb + O_X + doff[r], xv0 + soff[r]);
        CP_COMMIT();
    }
    float2 esp_next = g_esp[i * 2][((long)b * 256 + tid) * 8 + 0];
    for (int idx = tid; idx < 512; idx += 256) {
        int j = idx >> 8, rem = idx & 255;
        int tt = rem >> 3, h = rem & 7;
        edp_sm[idx] = g_edp[i * 2 + j][((long)b * 256 + t0 + tt) * 8 + h];
    }
    __syncthreads();
    // transpose mask bits: maskT[j*256 + tp*8 + w] bit (s&31), s = w*32+lane
    for (int step = 0; step < 64; step++) {
        int word_id = step * 8 + wid;
        int j = word_id >> 8, rem = word_id & 255;
        int tp = rem >> 3, wv = rem & 7;
        unsigned bit = (mtmp[j * 256 + wv * 32 + lane] >> tp) & 1u;
        unsigned w = __ballot_sync(0xffffffffu, bit);
        if (lane == 0) maskT[word_id] = w;
    }
    __syncthreads();
    esp_sm[tid] = esp_next;
    __syncthreads();

    for (int h = 0; h < 8; h++) {
        float cres[4] = {0.f, 0.f, 0.f, 0.f};
        for (int j = 0; j < 2; j++) {
            const int it = h * 2 + j;
            const int p = it & 1;

            // start next iteration's X staging + esp prefetch
            if (it < 15) {
                const int itn = it + 1;
                const int hn = itn >> 1, jn = itn & 1;
                const __nv_bfloat16* src_base = (jn ? xv1 : xv0) + hn * 8192;
                uint32_t dbase = sb + O_X + (itn & 1) * XBUF;
                #pragma unroll
                for (int r = 0; r < 4; r++)
                    CP_ASYNC16(dbase + doff[r], src_base + soff[r]);
                CP_COMMIT();
                esp_next = g_esp[i * 2 + jn][((long)b * 256 + tid) * 8 + hn];
            }

            // ---- weight loop: e = sel(mask, sel(es*ed>=1, es*ed, es2*ed2), 1) ----
            {
                float es[8], es2[8];
                #pragma unroll
                for (int rp = 0; rp < 4; rp++) {
                    float4 q = *(const float4*)&esp_sm[lane * 8 + rp * 2];
                    es[rp * 2]     = q.x; es2[rp * 2]     = q.y;
                    es[rp * 2 + 1] = q.z; es2[rp * 2 + 1] = q.w;
                }
                const int bb = (lane & 3) * 8;
                #pragma unroll
                for (int kk = 0; kk < 4; kk++) {
                    int tp = wid + kk * 8;
                    float2 ed = edp_sm[j * 256 + tp * 8 + h];
                    unsigned mword = maskT[j * 256 + tp * 8 + (lane >> 2)];
                    float e[8];
                    #pragma unroll
                    for (int r = 0; r < 8; r++) {
                        float m0 = es[r] * ed.x;            // exp(as+ad)
                        float m1 = es2[r] * ed.y;           // exp(0.2(as+ad))
                        float v = (m0 >= 1.0f) ? m0 : m1;   // leaky through exp
                        e[r] = ((mword >> (bb + r)) & 1u) ? v : 1.0f;  // masked -> exp(0)
                    }
                    uint32_t ph[4], pl[4];
                    #pragma unroll
                    for (int pq = 0; pq < 4; pq++) {
                        __nv_bfloat162 h2 = __floats2bfloat162_rn(e[pq * 2], e[pq * 2 + 1]);
                        uint32_t hbits = *(uint32_t*)&h2;
                        ph[pq] = hbits;
                        float f0 = __uint_as_float(hbits << 16);
                        float f1 = __uint_as_float(hbits & 0xFFFF0000u);
                        __nv_bfloat162 l2 = __floats2bfloat162_rn(e[pq * 2] - f0,
                                                                  e[pq * 2 + 1] - f1);
                        pl[pq] = *(uint32_t*)&l2;
                    }
                    *(uint4*)&Wh[tp * LDA_A + lane * 8] = make_uint4(ph[0], ph[1], ph[2], ph[3]);
                    *(uint4*)&Wl[tp * LDA_A + lane * 8] = make_uint4(pl[0], pl[1], pl[2], pl[3]);
                }
            }
            if (it < 15) { CP_WAIT1(); } else { CP_WAIT0(); }
            __syncthreads();

            // ---- AV + denominator: c = (ph+pl)@Xh ; den = (ph+pl)@ones ----
            const uint32_t aBh = sb + O_X + p * XBUF + bOffInRow;
            float c[4] = {0.f, 0.f, 0.f, 0.f};
            float den[4] = {0.f, 0.f, 0.f, 0.f};
            #pragma unroll
            for (int kt = 0; kt < 16; kt++) {
                const uint32_t off = kt * 32;
                uint32_t ah0, ah1, ah2, ah3, al0, al1, al2, al3;
                uint32_t bh0, bh1;
                ldsm_x4(ah0, ah1, ah2, ah3, aAh + off);
                ldsm_x4(al0, al1, al2, al3, aAh + (O_WL - O_WH) + off);
                ldsm_x2(bh0, bh1, aBh + off);
                mma16816(c, ah0, ah1, ah2, ah3, bh0, bh1);
                mma16816(c, al0, al1, al2, al3, bh0, bh1);
                mma16816(den, ah0, ah1, ah2, ah3, ONES_BF16X2, ONES_BF16X2);
                mma16816(den, al0, al1, al2, al3, ONES_BF16X2, ONES_BF16X2);
            }
            float inv0 = __fdividef(1.0f, den[0]);
            float inv1 = __fdividef(1.0f, den[2]);
            cres[0] += c[0] * inv0;
            cres[1] += c[1] * inv0;
            cres[2] += c[2] * inv1;
            cres[3] += c[3] * inv1;

            if (it < 15) esp_sm[tid] = esp_next;
            __syncthreads();
        }
        // epilogue: + residual xp0 + xp1 + gbias(both convs)
        {
            int t = t0 + mt * 16 + r4;
            int dfull = h * 32 + nt * 8 + c2;
            const float* xp0 = g_xp[i * 2 + 0];
            const float* xp1 = g_xp[i * 2 + 1];
            float2 gb0 = *(const float2*)&gbias[(i * 2 + 0) * 256 + dfull];
            float2 gb1 = *(const float2*)&gbias[(i * 2 + 1) * 256 + dfull];
            float gbx = gb0.x + gb1.x, gby = gb0.y + gb1.y;
            long r0 = ((long)b * 256 + t) * 256 + dfull;
            long r1 = ((long)b * 256 + t + 8) * 256 + dfull;
            float2 x00 = *(const float2*)&xp0[r0];
            float2 x01 = *(const float2*)&xp1[r0];
            float2 x10 = *(const float2*)&xp0[r1];
            float2 x11 = *(const float2*)&xp1[r1];
            float2 o0, o1;
            o0.x = cres[0] + x00.x + x01.x + gbx;
            o0.y = cres[1] + x00.y + x01.y + gby;
            o1.x = cres[2] + x10.x + x11.x + gbx;
            o1.y = cres[3] + x10.y + x11.y + gby;
            long ob = ((long)(b * ORD + i) * 256 + t) * 256 + dfull;
            *(float2*)&out[ob] = o0;
            *(float2*)&out[ob + 8 * 256] = o1;
        }
    }
}

// ---------------------------------------------------------------------------
// final: out = prelu(h + mean_over_order(h)), in place
// ---------------------------------------------------------------------------
__global__ void final_kernel(float* __restrict__ out,
                             const float* __restrict__ prelu_a) {
    int idx = blockIdx.x * 256 + threadIdx.x;
    if (idx >= B_ * S_ * D_) return;
    int d = idx & 255;
    int bs = idx >> 8;
    int b = bs >> 8, s = bs & 255;
    long i0 = ((long)(b * ORD + 0) * S_ + s) * D_ + d;
    long i1 = ((long)(b * ORD + 1) * S_ + s) * D_ + d;
    float h0 = out[i0];
    float h1 = out[i1];
    float m = 0.5f * (h0 + h1);
    float a = prelu_a[d];
    float o0 = h0 + m, o1 = h1 + m;
    o0 = o0 >= 0.f ? o0 : a * o0;
    o1 = o1 >= 0.f ? o1 : a * o1;
    out[i0] = o0;
    out[i1] = o1;
}

// ---------------------------------------------------------------------------
extern "C" void kernel_launch(void* const* d_in, const int* in_sizes, int n_in,
                              void* d_out, int out_size) {
    const float* x        = (const float*)d_in[0];
    const int*   A        = (const int*)  d_in[1];
    const float* Wp       = (const float*)d_in[2];
    const float* bp       = (const float*)d_in[3];
    const float* att_src  = (const float*)d_in[4];
    const float* att_dst  = (const float*)d_in[5];
    const float* gbias    = (const float*)d_in[6];
    const float* prelu_a  = (const float*)d_in[7];
    float* out = (float*)d_out;

    cudaFuncSetAttribute(attn_kernel,
                         cudaFuncAttributeMaxDynamicSharedMemorySize, A_TOTAL);
    cudaFuncSetAttribute(proj_mma_kernel,
                         cudaFuncAttributeMaxDynamicSharedMemorySize, P_TOTAL);

    convert_x_kernel<<<(B_ * ORD * S_ * D_ / 4 + 255) / 256, 256>>>(x);
    convert_w_kernel<<<(4 * D_ * D_ + 255) / 256, 256>>>(Wp);
    proj_mma_kernel<<<dim3(M_ / 128, D_ / 64, 4), 256, P_TOTAL>>>(bp, att_src, att_dst);
    attn_kernel<<<dim3(8, ORD, B_), 256, A_TOTAL>>>(A, gbias, out);
    final_kernel<<<(B_ * S_ * D_ + 255) / 256, 256>>>(out, prelu_a);
}

// round 17
// speedup vs baseline: 1.0856x; 1.0856x over previous
#include <cuda_runtime.h>
#include <cuda_bf16.h>
#include <cstdint>

#define B_   64
#define ORD  2
#define S_   256
#define D_   256
#define H_   8
#define HD_  32
#define M_   (B_ * S_)
#define LOG2E 1.44269504088896f

// ---------------- device scratch (allocation-free) ----------------
__device__ float g_xp[4][M_ * D_];            // projected x (+bias), fp32
__device__ float g_as[4][M_ * H_];            // per-source scores (pre-scaled by log2e)
__device__ float g_ad[4][M_ * H_];            // per-dest scores (pre-scaled by log2e)
__device__ __nv_bfloat16 g_xh[2][M_ * D_];    // x split hi  [m][k]
__device__ __nv_bfloat16 g_xl[2][M_ * D_];    // x split lo
__device__ __nv_bfloat16 g_wh[4][D_ * D_];    // W^T split hi [n][k]
__device__ __nv_bfloat16 g_wl[4][D_ * D_];    // W^T split lo
__device__ __nv_bfloat16 g_xvh[4][M_ * D_];   // values transposed bf16 [(b*H+h)*HD+d][s]

// ---------------- helpers ----------------
__device__ __forceinline__ uint32_t smem_u32(const void* p) {
    uint32_t a;
    asm("{ .reg .u64 t; cvta.to.shared.u64 t, %1; cvt.u32.u64 %0, t; }"
        : "=r"(a) : "l"(p));
    return a;
}
__device__ __forceinline__ void mma16816(float* c, const uint32_t a0, const uint32_t a1,
                                         const uint32_t a2, const uint32_t a3,
                                         const uint32_t b0, const uint32_t b1) {
    asm volatile(
        "mma.sync.aligned.m16n8k16.row.col.f32.bf16.bf16.f32 "
        "{%0,%1,%2,%3}, {%4,%5,%6,%7}, {%8,%9}, {%0,%1,%2,%3};"
        : "+f"(c[0]), "+f"(c[1]), "+f"(c[2]), "+f"(c[3])
        : "r"(a0), "r"(a1), "r"(a2), "r"(a3), "r"(b0), "r"(b1));
}
__device__ __forceinline__ void ldsm_x4(uint32_t& r0, uint32_t& r1, uint32_t& r2,
                                        uint32_t& r3, uint32_t addr) {
    asm volatile("ldmatrix.sync.aligned.m8n8.x4.shared.b16 {%0,%1,%2,%3}, [%4];"
                 : "=r"(r0), "=r"(r1), "=r"(r2), "=r"(r3) : "r"(addr));
}
__device__ __forceinline__ void ldsm_x2(uint32_t& r0, uint32_t& r1, uint32_t addr) {
    asm volatile("ldmatrix.sync.aligned.m8n8.x2.shared.b16 {%0,%1}, [%2];"
                 : "=r"(r0), "=r"(r1) : "r"(addr));
}
__device__ __forceinline__ float ex2f(float x) {
    float r;
    asm("ex2.approx.f32 %0, %1;" : "=f"(r) : "f"(x));
    return r;
}
#define CP_ASYNC16(dst, src) \
    asm volatile("cp.async.ca.shared.global [%0], [%1], 16;" \
                 :: "r"(dst), "l"(src) : "memory")
#define CP_COMMIT() asm volatile("cp.async.commit_group;" ::: "memory")
#define CP_WAIT1() asm volatile("cp.async.wait_group 1;" ::: "memory")
#define CP_WAIT0() asm volatile("cp.async.wait_group 0;" ::: "memory")

// ---------------------------------------------------------------------------
// split-conversion kernels
// ---------------------------------------------------------------------------
__global__ void convert_x_kernel(const float* __restrict__ x) {
    long q = (long)blockIdx.x * 256 + threadIdx.x;   // float4 index
    float4 v = ((const float4*)x)[q];
    long e = q * 4;
    int d = (int)(e & 255);
    long sd = e >> 8;
    int s = (int)(sd & 255);
    int bi = (int)(sd >> 8);
    int i = bi & 1, b = bi >> 1;
    long o = ((long)(b * 256 + s)) * 256 + d;
    union { __nv_bfloat16 h[4]; uint2 u; } ph, pl;
    float f[4] = {v.x, v.y, v.z, v.w};
    #pragma unroll
    for (int t = 0; t < 4; t++) {
        __nv_bfloat16 hi = __float2bfloat16(f[t]);
        ph.h[t] = hi;
        pl.h[t] = __float2bfloat16(f[t] - __bfloat162float(hi));
    }
    *(uint2*)&g_xh[i][o] = ph.u;
    *(uint2*)&g_xl[i][o] = pl.u;
}

__global__ void convert_w_kernel(const float* __restrict__ Wp) {
    int idx = blockIdx.x * 256 + threadIdx.x;   // 4*65536 total
    int ij = idx >> 16;
    int r = idx & 65535;
    int k = r >> 8, n = r & 255;
    float v = Wp[idx];
    __nv_bfloat16 hi = __float2bfloat16(v);
    g_wh[ij][n * 256 + k] = hi;
    g_wl[ij][n * 256 + k] = __float2bfloat16(v - __bfloat162float(hi));
}

// ---------------------------------------------------------------------------
// projection via mma.sync, cp.async double-buffered staging,
// + fused scores (pre-scaled by log2e) + transposed value emit (bf16)
// grid (M/128, D/64, 4), 256 threads (8 warps, wm 0..3 x wn 0..1)
// ---------------------------------------------------------------------------
#define LDA_P 40    // padded k-stride (bf16 elems)
#define LDT_P 136   // padded s-stride for transpose stage
#define PSTG  30720
#define P_TOTAL (2 * PSTG)
__global__ void __launch_bounds__(256) proj_mma_kernel(
        const float* __restrict__ bp,
        const float* __restrict__ att_src,
        const float* __restrict__ att_dst) {
    extern __shared__ __align__(16) char psm[];
    __nv_bfloat16* Th = (__nv_bfloat16*)(psm);   // 64*136*2 = 17408 B reuse

    const int tid = threadIdx.x;
    const int wid = tid >> 5, lane = tid & 31;
    const int wm = wid & 3, wn = wid >> 2;
    const int m0 = blockIdx.x * 128;
    const int n0 = blockIdx.y * 64;
    const int ij = blockIdx.z;
    const int i = ij >> 1;
    const int r4 = lane >> 2, c2 = (lane & 3) * 2;
    const int b = m0 >> 8, s0 = m0 & 255;
    const int h0 = n0 >> 5;
    const int hw = h0 + wn;

    const __nv_bfloat16* xh = g_xh[i];
    const __nv_bfloat16* xl = g_xl[i];
    const __nv_bfloat16* wh = g_wh[ij];
    const __nv_bfloat16* wl = g_wl[ij];

    const uint32_t sb = smem_u32(psm);
    const int tq = lane >> 3, rq = lane & 7;
    uint32_t aA0[2], aB0[2];
    #pragma unroll
    for (int mt = 0; mt < 2; mt++)
        aA0[mt] = sb + ((wm * 32 + mt * 16 + (tq & 1) * 8 + rq) * LDA_P
                        + (tq >> 1) * 8) * 2;
    #pragma unroll
    for (int np = 0; np < 2; np++)
        aB0[np] = sb + 20480 + ((wn * 32 + np * 16 + (tq & 1) * 8 + rq) * LDA_P
                                + (tq >> 1) * 8) * 2;

    const int arow = tid >> 2, apart = tid & 3;
    const int brow = tid >> 2, bpart = tid & 3;

    float c[2][4][4] = {};

    // prologue: stage kc=0 into buffer 0
    {
        #pragma unroll
        for (int r = 0; r < 2; r++) {
            int row = arow + r * 64;
            long gi = (long)(m0 + row) * 256 + apart * 8;
            uint32_t dst = sb + row * 80 + apart * 16;
            CP_ASYNC16(dst, xh + gi);
            CP_ASYNC16(dst + 10240, xl + gi);
        }
        {
            long gi = (long)(n0 + brow) * 256 + bpart * 8;
            uint32_t dst = sb + 20480 + brow * 80 + bpart * 16;
            CP_ASYNC16(dst, wh + gi);
            CP_ASYNC16(dst + 5120, wl + gi);
        }
        CP_COMMIT();
    }

    for (int kc = 0; kc < 8; kc++) {
        const uint32_t boff = (kc & 1) * PSTG;
        CP_WAIT0();
        __syncthreads();
        if (kc < 7) {
            const int k0 = (kc + 1) * 32;
            const uint32_t nboff = ((kc + 1) & 1) * PSTG;
            #pragma unroll
            for (int r = 0; r < 2; r++) {
                int row = arow + r * 64;
                long gi = (long)(m0 + row) * 256 + k0 + apart * 8;
                uint32_t dst = sb + nboff + row * 80 + apart * 16;
                CP_ASYNC16(dst, xh + gi);
                CP_ASYNC16(dst + 10240, xl + gi);
            }
            {
                long gi = (long)(n0 + brow) * 256 + k0 + bpart * 8;
                uint32_t dst = sb + nboff + 20480 + brow * 80 + bpart * 16;
                CP_ASYNC16(dst, wh + gi);
                CP_ASYNC16(dst + 5120, wl + gi);
            }
            CP_COMMIT();
        }

        #pragma unroll
        for (int kt = 0; kt < 2; kt++) {
            const uint32_t off = boff + kt * 32;
            uint32_t ah[2][4], al[2][4], bh[4][2], bl[4][2];
            #pragma unroll
            for (int mt = 0; mt < 2; mt++) {
                ldsm_x4(ah[mt][0], ah[mt][1], ah[mt][2], ah[mt][3], aA0[mt] + off);
                ldsm_x4(al[mt][0], al[mt][1], al[mt][2], al[mt][3], aA0[mt] + 10240 + off);
            }
            #pragma unroll
            for (int np = 0; np < 2; np++) {
                ldsm_x4(bh[2 * np][0], bh[2 * np + 1][0],
                        bh[2 * np][1], bh[2 * np + 1][1], aB0[np] + off);
                ldsm_x4(bl[2 * np][0], bl[2 * np + 1][0],
                        bl[2 * np][1], bl[2 * np + 1][1], aB0[np] + 5120 + off);
            }
            #pragma unroll
            for (int mt = 0; mt < 2; mt++)
                #pragma unroll
                for (int nt = 0; nt < 4; nt++) {
                    mma16816(c[mt][nt], ah[mt][0], ah[mt][1], ah[mt][2], ah[mt][3],
                             bh[nt][0], bh[nt][1]);
                    mma16816(c[mt][nt], ah[mt][0], ah[mt][1], ah[mt][2], ah[mt][3],
                             bl[nt][0], bl[nt][1]);
                    mma16816(c[mt][nt], al[mt][0], al[mt][1], al[mt][2], al[mt][3],
                             bh[nt][0], bh[nt][1]);
                }
        }
    }

    // ---- epilogue: bias, store xp, fused scores (x log2e), bf16 transpose ----
    float asw[4][2], adw[4][2];
    #pragma unroll
    for (int nt = 0; nt < 4; nt++) {
        int n = n0 + wn * 32 + nt * 8 + c2;
        float2 bb = *(const float2*)&bp[ij * 256 + n];
        float2 sw = *(const float2*)&att_src[ij * 256 + n];
        float2 dw = *(const float2*)&att_dst[ij * 256 + n];
        asw[nt][0] = sw.x; asw[nt][1] = sw.y;
        adw[nt][0] = dw.x; adw[nt][1] = dw.y;
        #pragma unroll
        for (int mt = 0; mt < 2; mt++) {
            c[mt][nt][0] += bb.x; c[mt][nt][1] += bb.y;
            c[mt][nt][2] += bb.x; c[mt][nt][3] += bb.y;
        }
    }
    float* xp = g_xp[ij];
    #pragma unroll
    for (int mt = 0; mt < 2; mt++) {
        int m = m0 + wm * 32 + mt * 16 + r4;
        #pragma unroll
        for (int nt = 0; nt < 4; nt++) {
            int n = n0 + wn * 32 + nt * 8 + c2;
            *(float2*)&xp[(long)m * 256 + n]       = *(float2*)&c[mt][nt][0];
            *(float2*)&xp[(long)(m + 8) * 256 + n] = *(float2*)&c[mt][nt][2];
        }
    }
    #pragma unroll
    for (int mt = 0; mt < 2; mt++)
        #pragma unroll
        for (int rr = 0; rr < 2; rr++) {
            float vs = 0.f, vd = 0.f;
            #pragma unroll
            for (int nt = 0; nt < 4; nt++) {
                vs += c[mt][nt][rr * 2 + 0] * asw[nt][0]
                    + c[mt][nt][rr * 2 + 1] * asw[nt][1];
                vd += c[mt][nt][rr * 2 + 0] * adw[nt][0]
                    + c[mt][nt][rr * 2 + 1] * adw[nt][1];
            }
            vs += __shfl_xor_sync(0xffffffffu, vs, 1);
            vs += __shfl_xor_sync(0xffffffffu, vs, 2);
            vd += __shfl_xor_sync(0xffffffffu, vd, 1);
            vd += __shfl_xor_sync(0xffffffffu, vd, 2);
            if ((lane & 3) == 0) {
                int m = m0 + wm * 32 + mt * 16 + rr * 8 + r4;
                g_as[ij][(long)m * 8 + hw] = vs * LOG2E;
                g_ad[ij][(long)m * 8 + hw] = vd * LOG2E;
            }
        }
    __syncthreads();
    #pragma unroll
    for (int mt = 0; mt < 2; mt++)
        #pragma unroll
        for (int nt = 0; nt < 4; nt++)
            #pragma unroll
            for (int rr = 0; rr < 2; rr++)
                #pragma unroll
                for (int cc = 0; cc < 2; cc++) {
                    float v = c[mt][nt][rr * 2 + cc];
                    int dl = wn * 32 + nt * 8 + c2 + cc;
                    int sl = wm * 32 + mt * 16 + rr * 8 + r4;
                    Th[dl * LDT_P + sl] = __float2bfloat16(v);
                }
    __syncthreads();
    for (int q = tid; q < 1024; q += 256) {
        int row = q >> 4, off = q & 15;
        int h = h0 + (row >> 5), d = row & 31;
        long go = ((long)((b * 8 + h) * 32 + d)) * 256 + s0 + off * 8;
        *(int4*)&g_xvh[ij][go] = *(int4*)&Th[row * LDT_P + off * 8];
    }
}

// ---------------------------------------------------------------------------
// attention: mask -> leaky -> ex2 -> AV with SWAPPED MMA roles:
//   out^T[d][t] = X^T[d][s] @ P^T[s][t]; A = values (1 ldsm_x4),
//   B = probs hi+lo (2 ldsm_x2), den via constant-ones A (load-free).
// grid (8 t-tiles, ORD, B), 256 threads. dynamic smem 74752 B, 3 CTAs/SM.
// ---------------------------------------------------------------------------
#define LDA_A 264  // padded s-stride (bf16 elems)
#define O_WH   0
#define O_WL   16896
#define O_X    33792   // 2 buffers x hi 16896
#define XBUF   16896
#define O_AS   67584
#define O_AD   68608
#define O_MT   70656   // maskT: [j][tp][w] bit s  (512 words)
#define O_MS   72704   // mask temp: [j][s] bit t' (512 words)
#define A_TOTAL 74752
#define ONES_BF16X2 0x3F803F80u

__global__ void __launch_bounds__(256, 3) attn_kernel(const int* __restrict__ A,
                            const float* __restrict__ gbias,
                            float* __restrict__ out) {
    const int t0 = blockIdx.x * 32;
    const int i  = blockIdx.y;
    const int b  = blockIdx.z;
    const int tid = threadIdx.x;
    const int lane = tid & 31, wid = tid >> 5;
    const int r4 = lane >> 2, c2 = (lane & 3) * 2;
    const int mt = wid & 1;       // d-half (16 rows of 32)
    const int nt = wid >> 1;      // t-tile (8 cols of 32)

    extern __shared__ __align__(16) char smc[];
    __nv_bfloat16* Wh = (__nv_bfloat16*)(smc + O_WH);
    __nv_bfloat16* Wl = (__nv_bfloat16*)(smc + O_WL);
    float* as_sm = (float*)(smc + O_AS);
    float* ad_sm = (float*)(smc + O_AD);
    unsigned* maskT = (unsigned*)(smc + O_MT);
    unsigned* mtmp  = (unsigned*)(smc + O_MS);

    const uint32_t sb = smem_u32(smc);
    const int tq = lane >> 3, rq = lane & 7;
    // A-operand (values X, [d][s]): per-warp d-rows mt*16..mt*16+15
    const uint32_t aXoff =
        (uint32_t)((mt * 16 + (tq & 1) * 8 + rq) * LDA_A + (tq >> 1) * 8) * 2;
    // B-operand (probs, [t][s]): per-warp t-rows nt*8..nt*8+7
    const uint32_t bW = sb + O_WH +
        (uint32_t)((nt * 8 + rq) * LDA_A + ((lane >> 3) & 1) * 8) * 2;

    // hoisted staging offsets (thread-constant)
    int soff[4];
    uint32_t doff[4];
    #pragma unroll
    for (int r = 0; r < 4; r++) {
        int q = r * 256 + tid;
        int d = q >> 5, sv = q & 31;
        soff[r] = d * 256 + sv * 8;
        doff[r] = (uint32_t)(d * LDA_A + sv * 8) * 2;
    }
    const __nv_bfloat16* xv0 = g_xvh[i * 2 + 0] + (long)b * 65536;
    const __nv_bfloat16* xv1 = g_xvh[i * 2 + 1] + (long)b * 65536;

    // ---- prologue: start X(h=0,j=0) into buffer 0 (4 x 16B per thread) ----
    {
        #pragma unroll
        for (int r = 0; r < 4; r++)
            CP_ASYNC16(sb + O_X + doff[r], xv0 + soff[r]);
        CP_COMMIT();
    }
    float as_next = g_as[i * 2][((long)b * 256 + tid) * 8 + 0];

    // ---- edge masks (both convs): mtmp[j*256+s] bit tp ----
    {
        const int* Abase = A + ((long)(b * ORD + i) * S_) * S_ + t0;
        for (int k = 0; k < 32; k++) {
            int s = wid * 32 + k;
            int a = Abase[s * S_ + lane];
            unsigned m1 = __ballot_sync(0xffffffffu, (a == 2) | (a == 4));
            unsigned m2 = __ballot_sync(0xffffffffu, (a == 3) | (a == 4));
            if (lane == 0) { mtmp[s] = m1; mtmp[256 + s] = m2; }
        }
    }
    for (int idx = tid; idx < 512; idx += 256) {
        int j = idx >> 8, rem = idx & 255;
        int tt = rem >> 3, h = rem & 7;
        ad_sm[idx] = g_ad[i * 2 + j][((long)b * 256 + t0 + tt) * 8 + h];
    }
    __syncthreads();
    // transpose mask bits: maskT[j*256 + tp*8 + w] bit (s&31), s = w*32+lane
    for (int step = 0; step < 64; step++) {
        int word_id = step * 8 + wid;
        int j = word_id >> 8, rem = word_id & 255;
        int tp = rem >> 3, wv = rem & 7;
        unsigned bit = (mtmp[j * 256 + wv * 32 + lane] >> tp) & 1u;
        unsigned w = __ballot_sync(0xffffffffu, bit);
        if (lane == 0) maskT[word_id] = w;
    }
    __syncthreads();
    as_sm[tid] = as_next;
    __syncthreads();

    for (int h = 0; h < 8; h++) {
        float cres[4] = {0.f, 0.f, 0.f, 0.f};
        for (int j = 0; j < 2; j++) {
            const int it = h * 2 + j;
            const int p = it & 1;

            // start next iteration's X staging + as prefetch
            if (it < 15) {
                const int itn = it + 1;
                const int hn = itn >> 1, jn = itn & 1;
                const __nv_bfloat16* src_base = (jn ? xv1 : xv0) + hn * 8192;
                uint32_t dbase = sb + O_X + (itn & 1) * XBUF;
                #pragma unroll
                for (int r = 0; r < 4; r++)
                    CP_ASYNC16(dbase + doff[r], src_base + soff[r]);
                CP_COMMIT();
                as_next = g_as[i * 2 + jn][((long)b * 256 + tid) * 8 + hn];
            }

            // ---- weight loop: 8 consecutive s per lane, 4 tp rows per warp ----
            {
                float4 asA = *(const float4*)&as_sm[lane * 8];
                float4 asB = *(const float4*)&as_sm[lane * 8 + 4];
                float as8[8] = {asA.x, asA.y, asA.z, asA.w, asB.x, asB.y, asB.z, asB.w};
                const int bb = (lane & 3) * 8;
                #pragma unroll
                for (int kk = 0; kk < 4; kk++) {
                    int tp = wid + kk * 8;
                    float adv = ad_sm[j * 256 + tp * 8 + h];
                    unsigned mword = maskT[j * 256 + tp * 8 + (lane >> 2)];
                    float e[8];
                    #pragma unroll
                    for (int r = 0; r < 8; r++) {
                        float a = as8[r] + adv;
                        a = fmaxf(a, 0.2f * a);                       // leaky_relu(0.2)
                        float vv = ((mword >> (bb + r)) & 1u) ? a : 0.f;
                        e[r] = ex2f(vv);                              // exp via ex2
                    }
                    uint32_t ph[4], pl[4];
                    #pragma unroll
                    for (int pq = 0; pq < 4; pq++) {
                        __nv_bfloat162 h2 = __floats2bfloat162_rn(e[pq * 2], e[pq * 2 + 1]);
                        uint32_t hbits = *(uint32_t*)&h2;
                        ph[pq] = hbits;
                        float f0 = __uint_as_float(hbits << 16);
                        float f1 = __uint_as_float(hbits & 0xFFFF0000u);
                        __nv_bfloat162 l2 = __floats2bfloat162_rn(e[pq * 2] - f0,
                                                                  e[pq * 2 + 1] - f1);
                        pl[pq] = *(uint32_t*)&l2;
                    }
                    *(uint4*)&Wh[tp * LDA_A + lane * 8] = make_uint4(ph[0], ph[1], ph[2], ph[3]);
                    *(uint4*)&Wl[tp * LDA_A + lane * 8] = make_uint4(pl[0], pl[1], pl[2], pl[3]);
                }
            }
            if (it < 15) { CP_WAIT1(); } else { CP_WAIT0(); }
            __syncthreads();

            // ---- AV (swapped roles): c[d][t] += X@Ph + X@Pl ; den = ones@P ----
            const uint32_t aX = sb + O_X + p * XBUF + aXoff;
            float c[4] = {0.f, 0.f, 0.f, 0.f};
            float den[4] = {0.f, 0.f, 0.f, 0.f};
            #pragma unroll
            for (int kt = 0; kt < 16; kt++) {
                const uint32_t off = kt * 32;
                uint32_t ax0, ax1, ax2, ax3;
                uint32_t bh0, bh1, bl0, bl1;
                ldsm_x4(ax0, ax1, ax2, ax3, aX + off);
                ldsm_x2(bh0, bh1, bW + off);
                ldsm_x2(bl0, bl1, bW + (O_WL - O_WH) + off);
                mma16816(c, ax0, ax1, ax2, ax3, bh0, bh1);
                mma16816(c, ax0, ax1, ax2, ax3, bl0, bl1);
                mma16816(den, ONES_BF16X2, ONES_BF16X2, ONES_BF16X2, ONES_BF16X2, bh0, bh1);
                mma16816(den, ONES_BF16X2, ONES_BF16X2, ONES_BF16X2, ONES_BF16X2, bl0, bl1);
            }
            float inv0 = __fdividef(1.0f, den[0]);   // col t = c2
            float inv1 = __fdividef(1.0f, den[1]);   // col t = c2+1
            cres[0] += c[0] * inv0;
            cres[1] += c[1] * inv1;
            cres[2] += c[2] * inv0;
            cres[3] += c[3] * inv1;

            if (it < 15) as_sm[tid] = as_next;
            __syncthreads();
        }
        // epilogue: + residual xp0 + xp1 + gbias(both convs); layout (d-row, t-col)
        {
            int tcol0 = t0 + nt * 8 + c2;
            int tcol1 = tcol0 + 1;
            int d0 = h * 32 + mt * 16 + r4;
            int d1 = d0 + 8;
            const float* xp0 = g_xp[i * 2 + 0];
            const float* xp1 = g_xp[i * 2 + 1];
            float gb0 = gbias[(i * 2 + 0) * 256 + d0] + gbias[(i * 2 + 1) * 256 + d0];
            float gb1 = gbias[(i * 2 + 0) * 256 + d1] + gbias[(i * 2 + 1) * 256 + d1];
            long rt0 = ((long)b * 256 + tcol0) * 256;
            long rt1 = ((long)b * 256 + tcol1) * 256;
            long ob0 = ((long)(b * ORD + i) * 256 + tcol0) * 256;
            long ob1 = ((long)(b * ORD + i) * 256 + tcol1) * 256;
            out[ob0 + d0] = cres[0] + xp0[rt0 + d0] + xp1[rt0 + d0] + gb0;
            out[ob1 + d0] = cres[1] + xp0[rt1 + d0] + xp1[rt1 + d0] + gb0;
            out[ob0 + d1] = cres[2] + xp0[rt0 + d1] + xp1[rt0 + d1] + gb1;
            out[ob1 + d1] = cres[3] + xp0[rt1 + d1] + xp1[rt1 + d1] + gb1;
        }
    }
}

// ---------------------------------------------------------------------------
// final: out = prelu(h + mean_over_order(h)), in place, float4
// ---------------------------------------------------------------------------
__global__ void final_kernel(float* __restrict__ out,
                             const float* __restrict__ prelu_a) {
    int q = blockIdx.x * 256 + threadIdx.x;     // float4 index over B*S*D/4
    if (q >= B_ * S_ * D_ / 4) return;
    int d4 = q & 63;
    int sd = q >> 6;
    int s = sd & 255, b = sd >> 8;
    long i0 = ((long)(b * ORD + 0) * S_ + s) * 64 + d4;
    long i1 = ((long)(b * ORD + 1) * S_ + s) * 64 + d4;
    float4 h0 = ((float4*)out)[i0];
    float4 h1 = ((float4*)out)[i1];
    float4 a = ((const float4*)prelu_a)[d4];
    float4 o0, o1;
    float m;
    m = 0.5f * (h0.x + h1.x); o0.x = h0.x + m; o1.x = h1.x + m;
    m = 0.5f * (h0.y + h1.y); o0.y = h0.y + m; o1.y = h1.y + m;
    m = 0.5f * (h0.z + h1.z); o0.z = h0.z + m; o1.z = h1.z + m;
    m = 0.5f * (h0.w + h1.w); o0.w = h0.w + m; o1.w = h1.w + m;
    o0.x = o0.x >= 0.f ? o0.x : a.x * o0.x;  o1.x = o1.x >= 0.f ? o1.x : a.x * o1.x;
    o0.y = o0.y >= 0.f ? o0.y : a.y * o0.y;  o1.y = o1.y >= 0.f ? o1.y : a.y * o1.y;
    o0.z = o0.z >= 0.f ? o0.z : a.z * o0.z;  o1.z = o1.z >= 0.f ? o1.z : a.z * o1.z;
    o0.w = o0.w >= 0.f ? o0.w : a.w * o0.w;  o1.w = o1.w >= 0.f ? o1.w : a.w * o1.w;
    ((float4*)out)[i0] = o0;
    ((float4*)out)[i1] = o1;
}

// ---------------------------------------------------------------------------
extern "C" void kernel_launch(void* const* d_in, const int* in_sizes, int n_in,
                              void* d_out, int out_size) {
    const float* x        = (const float*)d_in[0];
    const int*   A        = (const int*)  d_in[1];
    const float* Wp       = (const float*)d_in[2];
    const float* bp       = (const float*)d_in[3];
    const float* att_src  = (const float*)d_in[4];
    const float* att_dst  = (const float*)d_in[5];
    const float* gbias    = (const float*)d_in[6];
    const float* prelu_a  = (const float*)d_in[7];
    float* out = (float*)d_out;

    cudaFuncSetAttribute(attn_kernel,
                         cudaFuncAttributeMaxDynamicSharedMemorySize, A_TOTAL);
    cudaFuncSetAttribute(proj_mma_kernel,
                         cudaFuncAttributeMaxDynamicSharedMemorySize, P_TOTAL);

    convert_x_kernel<<<(B_ * ORD * S_ * D_ / 4 + 255) / 256, 256>>>(x);
    convert_w_kernel<<<(4 * D_ * D_ + 255) / 256, 256>>>(Wp);
    proj_mma_kernel<<<dim3(M_ / 128, D_ / 64, 4), 256, P_TOTAL>>>(bp, att_src, att_dst);
    attn_kernel<<<dim3(8, ORD, B_), 256, A_TOTAL>>>(A, gbias, out);
    final_kernel<<<(B_ * S_ * D_ / 4 + 255) / 256, 256>>>(out, prelu_a);
}